// round 16
// baseline (speedup 1.0000x reference)
#include <cuda_runtime.h>
#include <cuda_bf16.h>
#include <math.h>

#define BB 4096
#define TT 70
#define EE 300
#define HH 60
#define VV 120000
#define RR (BB*TT)   // 286720 rows

typedef unsigned long long ull;

// ---------------- scratch (static device memory; no allocations) ----------------
__device__ float g_proj  [(size_t)VV*480];       // P[v][480] = emb[v] @ [WihF;WihB]^T + bih
__device__ float g_h_lstm[(size_t)RR*120 + 64];  // [T][B][120]
__device__ float g_gi_gru[(size_t)RR*360];       // [T][B][360]
__device__ float g_h_gru [(size_t)RR*120];       // [B][T][120]
__device__ float g_ghf   [BB*HH];
__device__ float g_ghb   [BB*HH];

__device__ __forceinline__ float sigf(float x) { return 1.f / (1.f + __expf(-x)); }

// pack two floats -> bf16x2 (f_low in low half)
__device__ __forceinline__ unsigned pk_bf(float f_high, float f_low) {
    unsigned r;
    asm("cvt.rn.bf16x2.f32 %0, %1, %2;" : "=r"(r) : "f"(f_high), "f"(f_low));
    return r;
}
__device__ __forceinline__ void mma_bf16(float* d, const unsigned* a, const unsigned* b) {
    asm volatile(
        "mma.sync.aligned.m16n8k16.row.col.f32.bf16.bf16.f32 "
        "{%0,%1,%2,%3}, {%4,%5,%6,%7}, {%8,%9}, {%0,%1,%2,%3};"
        : "+f"(d[0]), "+f"(d[1]), "+f"(d[2]), "+f"(d[3])
        : "r"(a[0]), "r"(a[1]), "r"(a[2]), "r"(a[3]), "r"(b[0]), "r"(b[1]));
}

// ---- packed f32x2 helpers ----
__device__ __forceinline__ void fma2(ull& d, ull a, ull b) {
    asm("fma.rn.f32x2 %0, %1, %2, %0;" : "+l"(d) : "l"(a), "l"(b));
}
__device__ __forceinline__ ull dup2(float x) {
    ull r;
    unsigned u = __float_as_uint(x);
    asm("mov.b64 %0, {%1, %1};" : "=l"(r) : "r"(u));
    return r;
}
__device__ __forceinline__ float2 unpk2(ull v) {
    unsigned lo, hi;
    asm("mov.b64 {%0, %1}, %2;" : "=r"(lo), "=r"(hi) : "l"(v));
    return make_float2(__uint_as_float(lo), __uint_as_float(hi));
}
__device__ __forceinline__ void gbar(int id) {
    asm volatile("bar.sync %0, 64;" :: "r"(id) : "memory");
}
__device__ __forceinline__ unsigned smem_u32p(const void* p) {
    unsigned a;
    asm("{ .reg .u64 t; cvta.to.shared.u64 t, %1; cvt.u32.u64 %0, t; }" : "=r"(a) : "l"(p));
    return a;
}
__device__ __forceinline__ void cp16(unsigned daddr, const float* src, int bytes) {
    asm volatile("cp.async.ca.shared.global [%0], [%1], 16, %2;"
                 :: "r"(daddr), "l"(src), "r"(bytes) : "memory");
}

// ---------------- tensor-core GEMM (3xBF16 split, cp.async pipelined staging) --------
// smem u32 layout: [0..17408) split (2 bufs x 4 arrays x 16 x 136)
//                  [17408..26624) rawA (2 bufs x 128 x 36)
//                  [26624..35840) rawB
template<int MODE>
__global__ __launch_bounds__(256) void gemm_tc(
    const float* __restrict__ Ain,
    const float* __restrict__ W0, const float* __restrict__ W1,
    const float* __restrict__ bias0, const float* __restrict__ bias1)
{
    constexpr int N  = (MODE == 2) ? 480 : 360;
    constexpr int K  = (MODE == 2) ? 300 : 120;
    constexpr int NS = (MODE == 2) ? 240 : 180;
    constexpr int M  = (MODE == 2) ? VV  : RR;
    constexpr int TM = 128, TK = 32, RW = 136;
    constexpr int ARR = 16 * RW;
    constexpr int BUF = 4 * ARR;
    constexpr int RAWROW = 36;
    constexpr int RAWBUF = 128 * RAWROW;      // 4608 u32
    constexpr int RAWA = 2 * BUF;             // 17408
    constexpr int RAWB = RAWA + 2 * RAWBUF;   // 26624

    extern __shared__ unsigned smem_u[];
    __shared__ int rbase[TM];

    float* __restrict__ C = (MODE == 2) ? g_proj : g_gi_gru;
    const float* __restrict__ A = (MODE == 2) ? Ain : (const float*)g_h_lstm;

    const int m0 = blockIdx.x * TM;
    const int n0 = blockIdx.y * 128;
    const int tid = threadIdx.x;
    const int lane = tid & 31, warp = tid >> 5;
    const int gid = lane >> 2, tig = lane & 3;
    const int wm = (warp >> 1) * 32, wn = (warp & 1) * 64;

    const int srow = tid >> 1;
    const int sks  = (tid & 1) * 16;
    const int skp  = (tid & 1) * 8;

    for (int i = tid; i < TM; i += 256) {
        int r = m0 + i;
        if (r >= M) r = M - 1;
        rbase[i] = r * K;
    }
    __syncthreads();

    const unsigned sb = smem_u32p(smem_u);
    const int ngS = n0 + srow;
    const float* wpS = (ngS < NS) ? (W0 + (size_t)ngS * K)
                      : (ngS < N) ? (W1 + (size_t)(ngS - NS) * K) : nullptr;
    const float* arowp = A + rbase[srow];

    float d[2][8][4];
    #pragma unroll
    for (int mi = 0; mi < 2; mi++)
        #pragma unroll
        for (int ni = 0; ni < 8; ni++)
            #pragma unroll
            for (int q = 0; q < 4; q++) d[mi][ni][q] = 0.f;

    // ---- prologue: cp.async tile 0 into raw buf 0 ----
    {
        const unsigned baseA = sb + (RAWA + srow * RAWROW + sks) * 4;
        const unsigned baseB = sb + (RAWB + srow * RAWROW + sks) * 4;
        #pragma unroll
        for (int q = 0; q < 4; q++) {
            int kk = sks + q * 4;
            int bytes = (K - kk) * 4; bytes = bytes < 0 ? 0 : (bytes > 16 ? 16 : bytes);
            cp16(baseA + q * 16, arowp + (kk < K ? kk : K - 1), bytes);
            int bb = wpS ? bytes : 0;
            cp16(baseB + q * 16, wpS ? (wpS + (kk < K ? kk : K - 1)) : W0, bb);
        }
        asm volatile("cp.async.commit_group;" ::: "memory");
    }

    int it = 0;
    for (int k0 = 0; k0 < K; k0 += TK, it++) {
        const int bsel = it & 1;
        // ---- cp.async next tile into the other raw buffer ----
        {
            const int kn = k0 + TK;
            const int rb = bsel ^ 1;
            if (kn < K) {
                const unsigned baseA = sb + (RAWA + rb * RAWBUF + srow * RAWROW + sks) * 4;
                const unsigned baseB = sb + (RAWB + rb * RAWBUF + srow * RAWROW + sks) * 4;
                #pragma unroll
                for (int q = 0; q < 4; q++) {
                    int kk = kn + sks + q * 4;
                    int bytes = (K - kk) * 4; bytes = bytes < 0 ? 0 : (bytes > 16 ? 16 : bytes);
                    cp16(baseA + q * 16, arowp + (kk < K ? kk : K - 1), bytes);
                    int bb = wpS ? bytes : 0;
                    cp16(baseB + q * 16, wpS ? (wpS + (kk < K ? kk : K - 1)) : W0, bb);
                }
            }
            asm volatile("cp.async.commit_group;" ::: "memory");
            asm volatile("cp.async.wait_group 1;" ::: "memory");
        }

        unsigned* AH = smem_u + bsel * BUF;
        unsigned* AL = AH + ARR;
        unsigned* BH = AL + ARR;
        unsigned* BL = BH + ARR;

        // ---- convert raw (thread-private chunks) -> split buffers ----
        {
            const float* rwA = (const float*)smem_u + RAWA + bsel * RAWBUF + srow * RAWROW + sks;
            float xs[16];
            #pragma unroll
            for (int q = 0; q < 4; q++) *(float4*)&xs[q * 4] = *(const float4*)(rwA + q * 4);
            #pragma unroll
            for (int p = 0; p < 8; p++) {
                float f0 = xs[2 * p], f1 = xs[2 * p + 1];
                unsigned hi = pk_bf(f1, f0);
                float back0 = __uint_as_float(hi << 16);
                float back1 = __uint_as_float(hi & 0xffff0000u);
                AH[(skp + p) * RW + srow] = hi;
                AL[(skp + p) * RW + srow] = pk_bf(f1 - back1, f0 - back0);
            }
            const float* rwB = (const float*)smem_u + RAWB + bsel * RAWBUF + srow * RAWROW + sks;
            #pragma unroll
            for (int q = 0; q < 4; q++) *(float4*)&xs[q * 4] = *(const float4*)(rwB + q * 4);
            #pragma unroll
            for (int p = 0; p < 8; p++) {
                float f0 = xs[2 * p], f1 = xs[2 * p + 1];
                unsigned hi = pk_bf(f1, f0);
                float back0 = __uint_as_float(hi << 16);
                float back1 = __uint_as_float(hi & 0xffff0000u);
                BH[(skp + p) * RW + srow] = hi;
                BL[(skp + p) * RW + srow] = pk_bf(f1 - back1, f0 - back0);
            }
        }
        __syncthreads();

        #pragma unroll
        for (int kq = 0; kq < 2; kq++) {
            const int kpb = kq * 8;
            unsigned ah[2][4], al[2][4];
            #pragma unroll
            for (int mi = 0; mi < 2; mi++) {
                int r = wm + mi * 16 + gid;
                ah[mi][0] = AH[(kpb + tig) * RW + r];
                ah[mi][1] = AH[(kpb + tig) * RW + r + 8];
                ah[mi][2] = AH[(kpb + 4 + tig) * RW + r];
                ah[mi][3] = AH[(kpb + 4 + tig) * RW + r + 8];
                al[mi][0] = AL[(kpb + tig) * RW + r];
                al[mi][1] = AL[(kpb + tig) * RW + r + 8];
                al[mi][2] = AL[(kpb + 4 + tig) * RW + r];
                al[mi][3] = AL[(kpb + 4 + tig) * RW + r + 8];
            }
            #pragma unroll
            for (int ni = 0; ni < 8; ni++) {
                int cidx = wn + ni * 8 + gid;
                unsigned bh[2] = {BH[(kpb + tig) * RW + cidx], BH[(kpb + 4 + tig) * RW + cidx]};
                unsigned bl[2] = {BL[(kpb + tig) * RW + cidx], BL[(kpb + 4 + tig) * RW + cidx]};
                #pragma unroll
                for (int mi = 0; mi < 2; mi++) {
                    mma_bf16(d[mi][ni], ah[mi], bh);
                    mma_bf16(d[mi][ni], al[mi], bh);
                    mma_bf16(d[mi][ni], ah[mi], bl);
                }
            }
        }
    }

    #pragma unroll
    for (int mi = 0; mi < 2; mi++) {
        #pragma unroll
        for (int half = 0; half < 2; half++) {
            int mg = m0 + wm + mi * 16 + gid + half * 8;
            if (mg >= M) continue;
            float* crow = C + (size_t)mg * N;
            #pragma unroll
            for (int ni = 0; ni < 8; ni++) {
                int col = n0 + wn + ni * 8 + 2 * tig;
                if (col >= N) continue;
                float b0v = (col     < NS) ? bias0[col]     : bias1[col - NS];
                float b1v = (col + 1 < NS) ? bias0[col + 1] : bias1[col + 1 - NS];
                float2 v = make_float2(d[mi][ni][half * 2 + 0] + b0v,
                                       d[mi][ni][half * 2 + 1] + b1v);
                *(float2*)(crow + col) = v;
            }
        }
    }
}

// ---------------- LSTM recurrence: 4 decoupled 64-thread groups (R15) -------
__global__ __launch_bounds__(256, 2) void lstm_rec(
    const int* __restrict__ tokens,
    const float* __restrict__ WhhF, const float* __restrict__ bhhF,
    const float* __restrict__ WhhB, const float* __restrict__ bhhB)
{
    extern __shared__ float sm[];
    float* Wsh = sm;                    // [60][240]
    float* hsh = Wsh + 60 * 240;        // [4][2][60][8]
    int*   tsh = (int*)(hsh + 4 * 2 * 60 * 8);

    const int dir = blockIdx.x & 1;
    const int b0 = (blockIdx.x >> 1) * 32;
    const float* __restrict__ Whh = dir ? WhhB : WhhF;
    const float* __restrict__ bhh = dir ? bhhB : bhhF;
    const int tid = threadIdx.x;

    for (int i = tid; i < 240 * 60; i += 256) {
        int row = i / 60, j = i - row * 60;
        int gate = row / 60, h = row - gate * 60;
        Wsh[j * 240 + h * 4 + gate] = Whh[i];
    }
    for (int i = tid; i < 4 * 2 * 60 * 8; i += 256) hsh[i] = 0.f;
    for (int i = tid; i < 32 * TT; i += 256) tsh[i] = tokens[b0 * TT + i];

    const int g = tid >> 6;
    const int h = tid & 63;
    const bool active = h < 60;
    float bI = 0, bF = 0, bG = 0, bO = 0;
    if (active) { bI = bhh[h]; bF = bhh[60 + h]; bG = bhh[120 + h]; bO = bhh[180 + h]; }
    float c[8];
    #pragma unroll
    for (int b2 = 0; b2 < 8; b2++) c[b2] = 0.f;
    __syncthreads();

    float* gbase = hsh + g * 960;
    for (int s = 0; s < TT; s++) {
        const int t = dir ? (TT - 1 - s) : s;
        float* hcur = gbase + (s & 1) * 480;
        float* hnxt = gbase + ((s + 1) & 1) * 480;
        if (active) {
            float giI[8], giF[8], giG[8], giO[8];
            #pragma unroll
            for (int b2 = 0; b2 < 8; b2++) {
                int tok = tsh[(g * 8 + b2) * TT + t];
                const float* gp = g_proj + (size_t)tok * 480 + dir * 240;
                giI[b2] = gp[h]; giF[b2] = gp[60 + h];
                giG[b2] = gp[120 + h]; giO[b2] = gp[180 + h];
            }
            ull aI[4], aF[4], aG[4], aO[4];
            #pragma unroll
            for (int p = 0; p < 4; p++) { aI[p] = 0; aF[p] = 0; aG[p] = 0; aO[p] = 0; }
            #pragma unroll 10
            for (int j = 0; j < 60; j++) {
                float4 w = *(const float4*)&Wsh[j * 240 + h * 4];
                ull wi = dup2(w.x), wf = dup2(w.y), wg = dup2(w.z), wo = dup2(w.w);
                ulonglong2 hA = *(const ulonglong2*)&hcur[j * 8];
                ulonglong2 hB = *(const ulonglong2*)&hcur[j * 8 + 4];
                ull hv[4] = {hA.x, hA.y, hB.x, hB.y};
                #pragma unroll
                for (int p = 0; p < 4; p++) {
                    fma2(aI[p], wi, hv[p]);
                    fma2(aF[p], wf, hv[p]);
                    fma2(aG[p], wg, hv[p]);
                    fma2(aO[p], wo, hv[p]);
                }
            }
            float hvout[8];
            #pragma unroll
            for (int p = 0; p < 4; p++) {
                float2 vI = unpk2(aI[p]), vF = unpk2(aF[p]);
                float2 vG = unpk2(aG[p]), vO = unpk2(aO[p]);
                float aIv[2] = {vI.x, vI.y}, aFv[2] = {vF.x, vF.y};
                float aGv[2] = {vG.x, vG.y}, aOv[2] = {vO.x, vO.y};
                #pragma unroll
                for (int e = 0; e < 2; e++) {
                    int b2 = p * 2 + e;
                    float iv = sigf(giI[b2] + aIv[e] + bI);
                    float fv = sigf(giF[b2] + aFv[e] + bF);
                    float gv = tanhf(giG[b2] + aGv[e] + bG);
                    float ov = sigf(giO[b2] + aOv[e] + bO);
                    float cc = fmaf(fv, c[b2], iv * gv);
                    c[b2] = cc;
                    hvout[b2] = ov * tanhf(cc);
                    g_h_lstm[((size_t)t * BB + b0 + g * 8 + b2) * 120 + dir * 60 + h] = hvout[b2];
                }
            }
            *(float4*)&hnxt[h * 8]     = make_float4(hvout[0], hvout[1], hvout[2], hvout[3]);
            *(float4*)&hnxt[h * 8 + 4] = make_float4(hvout[4], hvout[5], hvout[6], hvout[7]);
        }
        gbar(g + 1);
    }
}

// ---------------- GRU recurrence: 4 decoupled 64-thread groups (R15) ----------------
__global__ __launch_bounds__(256, 2) void gru_rec(
    const float* __restrict__ WhhF, const float* __restrict__ bhhF,
    const float* __restrict__ WhhB, const float* __restrict__ bhhB)
{
    extern __shared__ float sm[];
    float* Wsh = sm;
    float* hsh = Wsh + 60 * 240;

    const int dir = blockIdx.x & 1;
    const int b0 = (blockIdx.x >> 1) * 32;
    const float* __restrict__ Whh = dir ? WhhB : WhhF;
    const float* __restrict__ bhh = dir ? bhhB : bhhF;
    const int tid = threadIdx.x;

    for (int i = tid; i < 180 * 60; i += 256) {
        int row = i / 60, j = i - row * 60;
        int gate = row / 60, h = row - gate * 60;
        Wsh[j * 240 + h * 4 + gate] = Whh[i];
    }
    for (int i = tid; i < 4 * 2 * 60 * 8; i += 256) hsh[i] = 0.f;

    const int g = tid >> 6;
    const int h = tid & 63;
    const bool active = h < 60;
    float bR = 0, bZ = 0, bN = 0;
    if (active) { bR = bhh[h]; bZ = bhh[60 + h]; bN = bhh[120 + h]; }
    float hp[8];
    #pragma unroll
    for (int b2 = 0; b2 < 8; b2++) hp[b2] = 0.f;
    __syncthreads();

    float* gbase = hsh + g * 960;
    for (int s = 0; s < TT; s++) {
        const int t = dir ? (TT - 1 - s) : s;
        float* hcur = gbase + (s & 1) * 480;
        float* hnxt = gbase + ((s + 1) & 1) * 480;
        if (active) {
            float giR[8], giZ[8], giN[8];
            #pragma unroll
            for (int b2 = 0; b2 < 8; b2++) {
                const float* gp = g_gi_gru + ((size_t)t * BB + b0 + g * 8 + b2) * 360 + dir * 180;
                giR[b2] = gp[h]; giZ[b2] = gp[60 + h]; giN[b2] = gp[120 + h];
            }
            ull aR[4], aZ[4], aN[4];
            #pragma unroll
            for (int p = 0; p < 4; p++) { aR[p] = 0; aZ[p] = 0; aN[p] = 0; }
            #pragma unroll 10
            for (int j = 0; j < 60; j++) {
                float4 w = *(const float4*)&Wsh[j * 240 + h * 4];
                ull wr = dup2(w.x), wz = dup2(w.y), wn = dup2(w.z);
                ulonglong2 hA = *(const ulonglong2*)&hcur[j * 8];
                ulonglong2 hB = *(const ulonglong2*)&hcur[j * 8 + 4];
                ull hv[4] = {hA.x, hA.y, hB.x, hB.y};
                #pragma unroll
                for (int p = 0; p < 4; p++) {
                    fma2(aR[p], wr, hv[p]);
                    fma2(aZ[p], wz, hv[p]);
                    fma2(aN[p], wn, hv[p]);
                }
            }
            float hvout[8];
            #pragma unroll
            for (int p = 0; p < 4; p++) {
                float2 vR = unpk2(aR[p]), vZ = unpk2(aZ[p]), vN = unpk2(aN[p]);
                float aRv[2] = {vR.x, vR.y}, aZv[2] = {vZ.x, vZ.y}, aNv[2] = {vN.x, vN.y};
                #pragma unroll
                for (int e = 0; e < 2; e++) {
                    int b2 = p * 2 + e;
                    int bgl = b0 + g * 8 + b2;
                    float r = sigf(giR[b2] + aRv[e] + bR);
                    float z = sigf(giZ[b2] + aZv[e] + bZ);
                    float n = tanhf(giN[b2] + r * (aNv[e] + bN));
                    float hv = (1.f - z) * n + z * hp[b2];
                    hp[b2] = hv;
                    hvout[b2] = hv;
                    g_h_gru[(size_t)bgl * TT * 120 + t * 120 + dir * 60 + h] = hv;
                    if (s == TT - 1) {
                        if (dir) g_ghb[bgl * 60 + h] = hv;
                        else     g_ghf[bgl * 60 + h] = hv;
                    }
                }
            }
            *(float4*)&hnxt[h * 8]     = make_float4(hvout[0], hvout[1], hvout[2], hvout[3]);
            *(float4*)&hnxt[h * 8 + 4] = make_float4(hvout[4], hvout[5], hvout[6], hvout[7]);
        }
        gbar(g + 1);
    }
}

// ---------------- final: attention + pools + linear + BN + out ----------------
__global__ __launch_bounds__(128) void final_kernel(
    const float* __restrict__ fin,
    const float* __restrict__ attn_w, const float* __restrict__ attn_b,
    const float* __restrict__ linW, const float* __restrict__ linb,
    const float* __restrict__ gamma, const float* __restrict__ beta,
    const float* __restrict__ mean, const float* __restrict__ var,
    const float* __restrict__ outW, const float* __restrict__ outb,
    float* __restrict__ out)
{
    __shared__ float hs[TT * 120];
    __shared__ float att[TT];
    __shared__ float conc[484];
    __shared__ float o16[16];
    __shared__ float asum_s;

    const int b = blockIdx.x;
    const int tid = threadIdx.x;
    const float* hp = g_h_gru + (size_t)b * TT * 120;

    for (int i = tid; i < TT * 120; i += 128) hs[i] = hp[i];
    __syncthreads();

    const int warp = tid >> 5, lane = tid & 31;
    for (int t = warp; t < TT; t += 4) {
        float s = 0.f;
        for (int k = lane; k < 120; k += 32) s = fmaf(hs[t * 120 + k], attn_w[k], s);
        #pragma unroll
        for (int o = 16; o > 0; o >>= 1) s += __shfl_xor_sync(0xffffffffu, s, o);
        if (lane == 0) att[t] = expf(tanhf(s) + attn_b[t]);
    }
    __syncthreads();
    if (tid == 0) {
        float s = 0.f;
        for (int t = 0; t < TT; t++) s += att[t];
        asum_s = s + 1e-10f;
    }
    __syncthreads();
    const float inva = 1.f / asum_s;

    if (tid < 120) {
        const int fidx = tid;
        float hat = 0.f, avg = 0.f, mx = -INFINITY;
        for (int t = 0; t < TT; t++) {
            float v = hs[t * 120 + fidx];
            hat = fmaf(v, att[t], hat);
            avg += v;
            mx = fmaxf(mx, v);
        }
        conc[120 + fidx] = hat * inva;
        conc[240 + fidx] = avg * (1.f / (float)TT);
        conc[360 + fidx] = mx;
        float hhv;
        int sub = (fidx >= 60) ? 1 : 0;
        int col = fidx - sub * 60;
        if (b < BB / 2) hhv = g_ghf[(2 * b + sub) * 60 + col];
        else            hhv = g_ghb[(2 * (b - BB / 2) + sub) * 60 + col];
        conc[fidx] = hhv;
    }
    if (tid == 0) conc[480] = fin[b];
    __syncthreads();

    if (tid < 16) {
        float s = linb[tid];
        const float* w = linW + tid * 481;
        for (int k = 0; k < 481; k++) s = fmaf(w[k], conc[k], s);
        s = fmaxf(s, 0.f);
        s = (s - mean[tid]) * rsqrtf(var[tid] + 1e-5f) * gamma[tid] + beta[tid];
        o16[tid] = s;
    }
    __syncthreads();
    if (tid == 0) {
        float s = outb[0];
        #pragma unroll
        for (int k = 0; k < 16; k++) s = fmaf(outW[k], o16[k], s);
        out[b] = s;
    }
}

// ---------------- launch ----------------
extern "C" void kernel_launch(void* const* d_in, const int* in_sizes, int n_in,
                              void* d_out, int out_size)
{
    const int*   tokens = (const int*)  d_in[0];
    const float* fin    = (const float*)d_in[1];
    const float* emb    = (const float*)d_in[2];
    const float* lWihF  = (const float*)d_in[3];
    const float* lWhhF  = (const float*)d_in[4];
    const float* lbihF  = (const float*)d_in[5];
    const float* lbhhF  = (const float*)d_in[6];
    const float* lWihB  = (const float*)d_in[7];
    const float* lWhhB  = (const float*)d_in[8];
    const float* lbihB  = (const float*)d_in[9];
    const float* lbhhB  = (const float*)d_in[10];
    const float* gWihF  = (const float*)d_in[11];
    const float* gWhhF  = (const float*)d_in[12];
    const float* gbihF  = (const float*)d_in[13];
    const float* gbhhF  = (const float*)d_in[14];
    const float* gWihB  = (const float*)d_in[15];
    const float* gWhhB  = (const float*)d_in[16];
    const float* gbihB  = (const float*)d_in[17];
    const float* gbhhB  = (const float*)d_in[18];
    const float* attnw  = (const float*)d_in[19];
    const float* attnb  = (const float*)d_in[20];
    const float* linW   = (const float*)d_in[21];
    const float* linb   = (const float*)d_in[22];
    const float* gamma  = (const float*)d_in[23];
    const float* beta   = (const float*)d_in[24];
    const float* mean   = (const float*)d_in[25];
    const float* var    = (const float*)d_in[26];
    const float* outW   = (const float*)d_in[27];
    const float* outb   = (const float*)d_in[28];
    float* out = (float*)d_out;

    const int gemm_smem = (2 * 4 * 16 * 136 + 4 * 128 * 36) * 4;  // 143360 B
    const int lstm_smem = (60*240 + 4*2*60*8) * 4 + 32*TT*4;       // 81920 B
    const int gru_smem  = (60*240 + 4*2*60*8) * 4;                 // 72960 B
    cudaFuncSetAttribute(gemm_tc<2>, cudaFuncAttributeMaxDynamicSharedMemorySize, gemm_smem);
    cudaFuncSetAttribute(gemm_tc<1>, cudaFuncAttributeMaxDynamicSharedMemorySize, gemm_smem);
    cudaFuncSetAttribute(lstm_rec, cudaFuncAttributeMaxDynamicSharedMemorySize, lstm_smem);
    cudaFuncSetAttribute(gru_rec,  cudaFuncAttributeMaxDynamicSharedMemorySize, gru_smem);

    gemm_tc<2><<<dim3((VV + 127) / 128, 4), 256, gemm_smem>>>(emb, lWihF, lWihB, lbihF, lbihB);
    lstm_rec<<<2 * (BB / 32), 256, lstm_smem>>>(tokens, lWhhF, lbhhF, lWhhB, lbhhB);
    gemm_tc<1><<<dim3(RR / 128, 3), 256, gemm_smem>>>(nullptr, gWihF, gWihB, gbihF, gbihB);
    gru_rec<<<2 * (BB / 32), 256, gru_smem>>>(gWhhF, gbhhF, gWhhB, gbhhB);
    final_kernel<<<BB, 128>>>(fin, attnw, attnb, linW, linb,
                              gamma, beta, mean, var, outW, outb, out);
}

// round 17
// speedup vs baseline: 1.1680x; 1.1680x over previous
#include <cuda_runtime.h>
#include <cuda_bf16.h>
#include <math.h>

#define BB 4096
#define TT 70
#define EE 300
#define HH 60
#define VV 120000
#define RR (BB*TT)   // 286720 rows

typedef unsigned long long ull;

// ---------------- scratch (static device memory; no allocations) ----------------
__device__ float g_proj  [(size_t)VV*480];       // P[v][480] = emb[v] @ [WihF;WihB]^T + bih
__device__ float g_h_lstm[(size_t)RR*120 + 64];  // [T][B][120]
__device__ float g_gi_gru[(size_t)RR*360];       // [T][B][360]
__device__ float g_h_gru [(size_t)RR*120];       // [B][T][120]
__device__ float g_ghf   [BB*HH];
__device__ float g_ghb   [BB*HH];

__device__ __forceinline__ float sigf(float x) { return 1.f / (1.f + __expf(-x)); }

// pack two floats -> bf16x2 (f_low in low half)
__device__ __forceinline__ unsigned pk_bf(float f_high, float f_low) {
    unsigned r;
    asm("cvt.rn.bf16x2.f32 %0, %1, %2;" : "=r"(r) : "f"(f_high), "f"(f_low));
    return r;
}
__device__ __forceinline__ void mma_bf16(float* d, const unsigned* a, const unsigned* b) {
    asm volatile(
        "mma.sync.aligned.m16n8k16.row.col.f32.bf16.bf16.f32 "
        "{%0,%1,%2,%3}, {%4,%5,%6,%7}, {%8,%9}, {%0,%1,%2,%3};"
        : "+f"(d[0]), "+f"(d[1]), "+f"(d[2]), "+f"(d[3])
        : "r"(a[0]), "r"(a[1]), "r"(a[2]), "r"(a[3]), "r"(b[0]), "r"(b[1]));
}

// ---- packed f32x2 helpers ----
__device__ __forceinline__ void fma2(ull& d, ull a, ull b) {
    asm("fma.rn.f32x2 %0, %1, %2, %0;" : "+l"(d) : "l"(a), "l"(b));
}
__device__ __forceinline__ ull dup2(float x) {
    ull r;
    unsigned u = __float_as_uint(x);
    asm("mov.b64 %0, {%1, %1};" : "=l"(r) : "r"(u));
    return r;
}
__device__ __forceinline__ float2 unpk2(ull v) {
    unsigned lo, hi;
    asm("mov.b64 {%0, %1}, %2;" : "=r"(lo), "=r"(hi) : "l"(v));
    return make_float2(__uint_as_float(lo), __uint_as_float(hi));
}
__device__ __forceinline__ void gbar(int id) {
    asm volatile("bar.sync %0, 64;" :: "r"(id) : "memory");
}

// ---------------- tensor-core GEMM (3xBF16 split, m16n8k16, double-buffered smem) ----
// (R15 known-good: LDG staging, single barrier per tile)
template<int MODE>
__global__ __launch_bounds__(256) void gemm_tc(
    const float* __restrict__ Ain,
    const float* __restrict__ W0, const float* __restrict__ W1,
    const float* __restrict__ bias0, const float* __restrict__ bias1)
{
    constexpr int N  = (MODE == 2) ? 480 : 360;
    constexpr int K  = (MODE == 2) ? 300 : 120;
    constexpr int NS = (MODE == 2) ? 240 : 180;
    constexpr int M  = (MODE == 2) ? VV  : RR;
    constexpr int TM = 128, TK = 32, RW = 136;
    constexpr int ARR = 16 * RW;
    constexpr int BUF = 4 * ARR;

    extern __shared__ unsigned smem_u[];
    __shared__ int rbase[TM];

    float* __restrict__ C = (MODE == 2) ? g_proj : g_gi_gru;
    const float* __restrict__ A = (MODE == 2) ? Ain : (const float*)g_h_lstm;

    const int m0 = blockIdx.x * TM;
    const int n0 = blockIdx.y * 128;
    const int tid = threadIdx.x;
    const int lane = tid & 31, warp = tid >> 5;
    const int gid = lane >> 2, tig = lane & 3;
    const int wm = (warp >> 1) * 32, wn = (warp & 1) * 64;

    const int srow = tid >> 1;
    const int sks  = (tid & 1) * 16;
    const int skp  = (tid & 1) * 8;

    for (int i = tid; i < TM; i += 256) {
        int r = m0 + i;
        if (r >= M) r = M - 1;
        rbase[i] = r * K;
    }
    __syncthreads();

    const int ngS = n0 + srow;
    const float* wpS = (ngS < NS) ? (W0 + (size_t)ngS * K)
                      : (ngS < N) ? (W1 + (size_t)(ngS - NS) * K) : nullptr;

    float d[2][8][4];
    #pragma unroll
    for (int mi = 0; mi < 2; mi++)
        #pragma unroll
        for (int ni = 0; ni < 8; ni++)
            #pragma unroll
            for (int q = 0; q < 4; q++) d[mi][ni][q] = 0.f;

    int it = 0;
    for (int k0 = 0; k0 < K; k0 += TK, it++) {
        const int bsel = it & 1;
        unsigned* AH = smem_u + bsel * BUF;
        unsigned* AL = AH + ARR;
        unsigned* BH = AL + ARR;
        unsigned* BL = BH + ARR;
        const bool fullk = (k0 + TK <= K);
        {
            float xs[16];
            if (fullk) {
                const float* ap = A + rbase[srow] + k0 + sks;
                #pragma unroll
                for (int q = 0; q < 4; q++) *(float4*)&xs[q * 4] = *(const float4*)(ap + q * 4);
            } else {
                #pragma unroll
                for (int e = 0; e < 16; e++) {
                    int kk = k0 + sks + e;
                    xs[e] = (kk < K) ? A[rbase[srow] + kk] : 0.f;
                }
            }
            #pragma unroll
            for (int p = 0; p < 8; p++) {
                float f0 = xs[2 * p], f1 = xs[2 * p + 1];
                unsigned hi = pk_bf(f1, f0);
                float back0 = __uint_as_float(hi << 16);
                float back1 = __uint_as_float(hi & 0xffff0000u);
                AH[(skp + p) * RW + srow] = hi;
                AL[(skp + p) * RW + srow] = pk_bf(f1 - back1, f0 - back0);
            }
        }
        {
            float xs[16];
            if (wpS && fullk) {
                #pragma unroll
                for (int q = 0; q < 4; q++) *(float4*)&xs[q * 4] = *(const float4*)(wpS + k0 + sks + q * 4);
            } else {
                #pragma unroll
                for (int e = 0; e < 16; e++) {
                    int kk = k0 + sks + e;
                    xs[e] = (wpS && kk < K) ? wpS[kk] : 0.f;
                }
            }
            #pragma unroll
            for (int p = 0; p < 8; p++) {
                float f0 = xs[2 * p], f1 = xs[2 * p + 1];
                unsigned hi = pk_bf(f1, f0);
                float back0 = __uint_as_float(hi << 16);
                float back1 = __uint_as_float(hi & 0xffff0000u);
                BH[(skp + p) * RW + srow] = hi;
                BL[(skp + p) * RW + srow] = pk_bf(f1 - back1, f0 - back0);
            }
        }
        __syncthreads();

        #pragma unroll
        for (int kq = 0; kq < 2; kq++) {
            const int kpb = kq * 8;
            unsigned ah[2][4], al[2][4];
            #pragma unroll
            for (int mi = 0; mi < 2; mi++) {
                int r = wm + mi * 16 + gid;
                ah[mi][0] = AH[(kpb + tig) * RW + r];
                ah[mi][1] = AH[(kpb + tig) * RW + r + 8];
                ah[mi][2] = AH[(kpb + 4 + tig) * RW + r];
                ah[mi][3] = AH[(kpb + 4 + tig) * RW + r + 8];
                al[mi][0] = AL[(kpb + tig) * RW + r];
                al[mi][1] = AL[(kpb + tig) * RW + r + 8];
                al[mi][2] = AL[(kpb + 4 + tig) * RW + r];
                al[mi][3] = AL[(kpb + 4 + tig) * RW + r + 8];
            }
            #pragma unroll
            for (int ni = 0; ni < 8; ni++) {
                int cidx = wn + ni * 8 + gid;
                unsigned bh[2] = {BH[(kpb + tig) * RW + cidx], BH[(kpb + 4 + tig) * RW + cidx]};
                unsigned bl[2] = {BL[(kpb + tig) * RW + cidx], BL[(kpb + 4 + tig) * RW + cidx]};
                #pragma unroll
                for (int mi = 0; mi < 2; mi++) {
                    mma_bf16(d[mi][ni], ah[mi], bh);
                    mma_bf16(d[mi][ni], al[mi], bh);
                    mma_bf16(d[mi][ni], ah[mi], bl);
                }
            }
        }
    }

    #pragma unroll
    for (int mi = 0; mi < 2; mi++) {
        #pragma unroll
        for (int half = 0; half < 2; half++) {
            int mg = m0 + wm + mi * 16 + gid + half * 8;
            if (mg >= M) continue;
            float* crow = C + (size_t)mg * N;
            #pragma unroll
            for (int ni = 0; ni < 8; ni++) {
                int col = n0 + wn + ni * 8 + 2 * tig;
                if (col >= N) continue;
                float b0v = (col     < NS) ? bias0[col]     : bias1[col - NS];
                float b1v = (col + 1 < NS) ? bias0[col + 1] : bias1[col + 1 - NS];
                float2 v = make_float2(d[mi][ni][half * 2 + 0] + b0v,
                                       d[mi][ni][half * 2 + 1] + b1v);
                *(float2*)(crow + col) = v;
            }
        }
    }
}

// ---------------- LSTM recurrence: 4 decoupled 64-thread groups (R15) -------
__global__ __launch_bounds__(256, 2) void lstm_rec(
    const int* __restrict__ tokens,
    const float* __restrict__ WhhF, const float* __restrict__ bhhF,
    const float* __restrict__ WhhB, const float* __restrict__ bhhB)
{
    extern __shared__ float sm[];
    float* Wsh = sm;                    // [60][240]
    float* hsh = Wsh + 60 * 240;        // [4][2][60][8]
    int*   tsh = (int*)(hsh + 4 * 2 * 60 * 8);

    const int dir = blockIdx.x & 1;
    const int b0 = (blockIdx.x >> 1) * 32;
    const float* __restrict__ Whh = dir ? WhhB : WhhF;
    const float* __restrict__ bhh = dir ? bhhB : bhhF;
    const int tid = threadIdx.x;

    for (int i = tid; i < 240 * 60; i += 256) {
        int row = i / 60, j = i - row * 60;
        int gate = row / 60, h = row - gate * 60;
        Wsh[j * 240 + h * 4 + gate] = Whh[i];
    }
    for (int i = tid; i < 4 * 2 * 60 * 8; i += 256) hsh[i] = 0.f;
    for (int i = tid; i < 32 * TT; i += 256) tsh[i] = tokens[b0 * TT + i];

    const int g = tid >> 6;
    const int h = tid & 63;
    const bool active = h < 60;
    float bI = 0, bF = 0, bG = 0, bO = 0;
    if (active) { bI = bhh[h]; bF = bhh[60 + h]; bG = bhh[120 + h]; bO = bhh[180 + h]; }
    float c[8];
    #pragma unroll
    for (int b2 = 0; b2 < 8; b2++) c[b2] = 0.f;
    __syncthreads();

    float* gbase = hsh + g * 960;
    for (int s = 0; s < TT; s++) {
        const int t = dir ? (TT - 1 - s) : s;
        float* hcur = gbase + (s & 1) * 480;
        float* hnxt = gbase + ((s + 1) & 1) * 480;
        if (active) {
            float giI[8], giF[8], giG[8], giO[8];
            #pragma unroll
            for (int b2 = 0; b2 < 8; b2++) {
                int tok = tsh[(g * 8 + b2) * TT + t];
                const float* gp = g_proj + (size_t)tok * 480 + dir * 240;
                giI[b2] = gp[h]; giF[b2] = gp[60 + h];
                giG[b2] = gp[120 + h]; giO[b2] = gp[180 + h];
            }
            ull aI[4], aF[4], aG[4], aO[4];
            #pragma unroll
            for (int p = 0; p < 4; p++) { aI[p] = 0; aF[p] = 0; aG[p] = 0; aO[p] = 0; }
            #pragma unroll 10
            for (int j = 0; j < 60; j++) {
                float4 w = *(const float4*)&Wsh[j * 240 + h * 4];
                ull wi = dup2(w.x), wf = dup2(w.y), wg = dup2(w.z), wo = dup2(w.w);
                ulonglong2 hA = *(const ulonglong2*)&hcur[j * 8];
                ulonglong2 hB = *(const ulonglong2*)&hcur[j * 8 + 4];
                ull hv[4] = {hA.x, hA.y, hB.x, hB.y};
                #pragma unroll
                for (int p = 0; p < 4; p++) {
                    fma2(aI[p], wi, hv[p]);
                    fma2(aF[p], wf, hv[p]);
                    fma2(aG[p], wg, hv[p]);
                    fma2(aO[p], wo, hv[p]);
                }
            }
            float hvout[8];
            #pragma unroll
            for (int p = 0; p < 4; p++) {
                float2 vI = unpk2(aI[p]), vF = unpk2(aF[p]);
                float2 vG = unpk2(aG[p]), vO = unpk2(aO[p]);
                float aIv[2] = {vI.x, vI.y}, aFv[2] = {vF.x, vF.y};
                float aGv[2] = {vG.x, vG.y}, aOv[2] = {vO.x, vO.y};
                #pragma unroll
                for (int e = 0; e < 2; e++) {
                    int b2 = p * 2 + e;
                    float iv = sigf(giI[b2] + aIv[e] + bI);
                    float fv = sigf(giF[b2] + aFv[e] + bF);
                    float gv = tanhf(giG[b2] + aGv[e] + bG);
                    float ov = sigf(giO[b2] + aOv[e] + bO);
                    float cc = fmaf(fv, c[b2], iv * gv);
                    c[b2] = cc;
                    hvout[b2] = ov * tanhf(cc);
                    g_h_lstm[((size_t)t * BB + b0 + g * 8 + b2) * 120 + dir * 60 + h] = hvout[b2];
                }
            }
            *(float4*)&hnxt[h * 8]     = make_float4(hvout[0], hvout[1], hvout[2], hvout[3]);
            *(float4*)&hnxt[h * 8 + 4] = make_float4(hvout[4], hvout[5], hvout[6], hvout[7]);
        }
        gbar(g + 1);
    }
}

// ---------------- GRU recurrence: 4 decoupled 64-thread groups (R15) ----------------
__global__ __launch_bounds__(256, 2) void gru_rec(
    const float* __restrict__ WhhF, const float* __restrict__ bhhF,
    const float* __restrict__ WhhB, const float* __restrict__ bhhB)
{
    extern __shared__ float sm[];
    float* Wsh = sm;
    float* hsh = Wsh + 60 * 240;

    const int dir = blockIdx.x & 1;
    const int b0 = (blockIdx.x >> 1) * 32;
    const float* __restrict__ Whh = dir ? WhhB : WhhF;
    const float* __restrict__ bhh = dir ? bhhB : bhhF;
    const int tid = threadIdx.x;

    for (int i = tid; i < 180 * 60; i += 256) {
        int row = i / 60, j = i - row * 60;
        int gate = row / 60, h = row - gate * 60;
        Wsh[j * 240 + h * 4 + gate] = Whh[i];
    }
    for (int i = tid; i < 4 * 2 * 60 * 8; i += 256) hsh[i] = 0.f;

    const int g = tid >> 6;
    const int h = tid & 63;
    const bool active = h < 60;
    float bR = 0, bZ = 0, bN = 0;
    if (active) { bR = bhh[h]; bZ = bhh[60 + h]; bN = bhh[120 + h]; }
    float hp[8];
    #pragma unroll
    for (int b2 = 0; b2 < 8; b2++) hp[b2] = 0.f;
    __syncthreads();

    float* gbase = hsh + g * 960;
    for (int s = 0; s < TT; s++) {
        const int t = dir ? (TT - 1 - s) : s;
        float* hcur = gbase + (s & 1) * 480;
        float* hnxt = gbase + ((s + 1) & 1) * 480;
        if (active) {
            float giR[8], giZ[8], giN[8];
            #pragma unroll
            for (int b2 = 0; b2 < 8; b2++) {
                const float* gp = g_gi_gru + ((size_t)t * BB + b0 + g * 8 + b2) * 360 + dir * 180;
                giR[b2] = gp[h]; giZ[b2] = gp[60 + h]; giN[b2] = gp[120 + h];
            }
            ull aR[4], aZ[4], aN[4];
            #pragma unroll
            for (int p = 0; p < 4; p++) { aR[p] = 0; aZ[p] = 0; aN[p] = 0; }
            #pragma unroll 10
            for (int j = 0; j < 60; j++) {
                float4 w = *(const float4*)&Wsh[j * 240 + h * 4];
                ull wr = dup2(w.x), wz = dup2(w.y), wn = dup2(w.z);
                ulonglong2 hA = *(const ulonglong2*)&hcur[j * 8];
                ulonglong2 hB = *(const ulonglong2*)&hcur[j * 8 + 4];
                ull hv[4] = {hA.x, hA.y, hB.x, hB.y};
                #pragma unroll
                for (int p = 0; p < 4; p++) {
                    fma2(aR[p], wr, hv[p]);
                    fma2(aZ[p], wz, hv[p]);
                    fma2(aN[p], wn, hv[p]);
                }
            }
            float hvout[8];
            #pragma unroll
            for (int p = 0; p < 4; p++) {
                float2 vR = unpk2(aR[p]), vZ = unpk2(aZ[p]), vN = unpk2(aN[p]);
                float aRv[2] = {vR.x, vR.y}, aZv[2] = {vZ.x, vZ.y}, aNv[2] = {vN.x, vN.y};
                #pragma unroll
                for (int e = 0; e < 2; e++) {
                    int b2 = p * 2 + e;
                    int bgl = b0 + g * 8 + b2;
                    float r = sigf(giR[b2] + aRv[e] + bR);
                    float z = sigf(giZ[b2] + aZv[e] + bZ);
                    float n = tanhf(giN[b2] + r * (aNv[e] + bN));
                    float hv = (1.f - z) * n + z * hp[b2];
                    hp[b2] = hv;
                    hvout[b2] = hv;
                    g_h_gru[(size_t)bgl * TT * 120 + t * 120 + dir * 60 + h] = hv;
                    if (s == TT - 1) {
                        if (dir) g_ghb[bgl * 60 + h] = hv;
                        else     g_ghf[bgl * 60 + h] = hv;
                    }
                }
            }
            *(float4*)&hnxt[h * 8]     = make_float4(hvout[0], hvout[1], hvout[2], hvout[3]);
            *(float4*)&hnxt[h * 8 + 4] = make_float4(hvout[4], hvout[5], hvout[6], hvout[7]);
        }
        gbar(g + 1);
    }
}

// ---------------- final: attention + pools + linear + BN + out (256 threads) ---------
__global__ __launch_bounds__(256) void final_kernel(
    const float* __restrict__ fin,
    const float* __restrict__ attn_w, const float* __restrict__ attn_b,
    const float* __restrict__ linW, const float* __restrict__ linb,
    const float* __restrict__ gamma, const float* __restrict__ beta,
    const float* __restrict__ mean, const float* __restrict__ var,
    const float* __restrict__ outW, const float* __restrict__ outb,
    float* __restrict__ out)
{
    __shared__ float hs[TT * 120];
    __shared__ float att[TT];
    __shared__ float conc[484];
    __shared__ float o16[16];
    __shared__ float asum_s;

    const int b = blockIdx.x;
    const int tid = threadIdx.x;
    const float* hp = g_h_gru + (size_t)b * TT * 120;

    for (int i = tid; i < TT * 120 / 4; i += 256)
        *(float4*)&hs[i * 4] = *(const float4*)(hp + i * 4);
    __syncthreads();

    const int warp = tid >> 5, lane = tid & 31;
    for (int t = warp; t < TT; t += 8) {
        float s = 0.f;
        for (int k = lane; k < 120; k += 32) s = fmaf(hs[t * 120 + k], attn_w[k], s);
        #pragma unroll
        for (int o = 16; o > 0; o >>= 1) s += __shfl_xor_sync(0xffffffffu, s, o);
        if (lane == 0) att[t] = expf(tanhf(s) + attn_b[t]);
    }
    __syncthreads();
    if (tid == 0) {
        float s = 0.f;
        for (int t = 0; t < TT; t++) s += att[t];
        asum_s = s + 1e-10f;
    }
    __syncthreads();
    const float inva = 1.f / asum_s;

    // 240 threads: fidx = tid%120, half of T each; combine via smem
    __shared__ float part[2][120][3];
    if (tid < 240) {
        const int fidx = tid % 120;
        const int hf = tid / 120;
        float hat = 0.f, avg = 0.f, mx = -INFINITY;
        for (int t = hf * 35; t < (hf + 1) * 35; t++) {
            float v = hs[t * 120 + fidx];
            hat = fmaf(v, att[t], hat);
            avg += v;
            mx = fmaxf(mx, v);
        }
        part[hf][fidx][0] = hat;
        part[hf][fidx][1] = avg;
        part[hf][fidx][2] = mx;
    }
    __syncthreads();
    if (tid < 120) {
        const int fidx = tid;
        conc[120 + fidx] = (part[0][fidx][0] + part[1][fidx][0]) * inva;
        conc[240 + fidx] = (part[0][fidx][1] + part[1][fidx][1]) * (1.f / (float)TT);
        conc[360 + fidx] = fmaxf(part[0][fidx][2], part[1][fidx][2]);
        float hhv;
        int sub = (fidx >= 60) ? 1 : 0;
        int col = fidx - sub * 60;
        if (b < BB / 2) hhv = g_ghf[(2 * b + sub) * 60 + col];
        else            hhv = g_ghb[(2 * (b - BB / 2) + sub) * 60 + col];
        conc[fidx] = hhv;
    }
    if (tid == 0) conc[480] = fin[b];
    __syncthreads();

    if (tid < 16) {
        float s = linb[tid];
        const float* w = linW + tid * 481;
        for (int k = 0; k < 481; k++) s = fmaf(w[k], conc[k], s);
        s = fmaxf(s, 0.f);
        s = (s - mean[tid]) * rsqrtf(var[tid] + 1e-5f) * gamma[tid] + beta[tid];
        o16[tid] = s;
    }
    __syncthreads();
    if (tid == 0) {
        float s = outb[0];
        #pragma unroll
        for (int k = 0; k < 16; k++) s = fmaf(outW[k], o16[k], s);
        out[b] = s;
    }
}

// ---------------- launch ----------------
extern "C" void kernel_launch(void* const* d_in, const int* in_sizes, int n_in,
                              void* d_out, int out_size)
{
    const int*   tokens = (const int*)  d_in[0];
    const float* fin    = (const float*)d_in[1];
    const float* emb    = (const float*)d_in[2];
    const float* lWihF  = (const float*)d_in[3];
    const float* lWhhF  = (const float*)d_in[4];
    const float* lbihF  = (const float*)d_in[5];
    const float* lbhhF  = (const float*)d_in[6];
    const float* lWihB  = (const float*)d_in[7];
    const float* lWhhB  = (const float*)d_in[8];
    const float* lbihB  = (const float*)d_in[9];
    const float* lbhhB  = (const float*)d_in[10];
    const float* gWihF  = (const float*)d_in[11];
    const float* gWhhF  = (const float*)d_in[12];
    const float* gbihF  = (const float*)d_in[13];
    const float* gbhhF  = (const float*)d_in[14];
    const float* gWihB  = (const float*)d_in[15];
    const float* gWhhB  = (const float*)d_in[16];
    const float* gbihB  = (const float*)d_in[17];
    const float* gbhhB  = (const float*)d_in[18];
    const float* attnw  = (const float*)d_in[19];
    const float* attnb  = (const float*)d_in[20];
    const float* linW   = (const float*)d_in[21];
    const float* linb   = (const float*)d_in[22];
    const float* gamma  = (const float*)d_in[23];
    const float* beta   = (const float*)d_in[24];
    const float* mean   = (const float*)d_in[25];
    const float* var    = (const float*)d_in[26];
    const float* outW   = (const float*)d_in[27];
    const float* outb   = (const float*)d_in[28];
    float* out = (float*)d_out;

    const int gemm_smem = 2 * 4 * 16 * 136 * 4;               // 69632 B
    const int lstm_smem = (60*240 + 4*2*60*8) * 4 + 32*TT*4;   // 81920 B
    const int gru_smem  = (60*240 + 4*2*60*8) * 4;             // 72960 B
    cudaFuncSetAttribute(gemm_tc<2>, cudaFuncAttributeMaxDynamicSharedMemorySize, gemm_smem);
    cudaFuncSetAttribute(gemm_tc<1>, cudaFuncAttributeMaxDynamicSharedMemorySize, gemm_smem);
    cudaFuncSetAttribute(lstm_rec, cudaFuncAttributeMaxDynamicSharedMemorySize, lstm_smem);
    cudaFuncSetAttribute(gru_rec,  cudaFuncAttributeMaxDynamicSharedMemorySize, gru_smem);

    gemm_tc<2><<<dim3((VV + 127) / 128, 4), 256, gemm_smem>>>(emb, lWihF, lWihB, lbihF, lbihB);
    lstm_rec<<<2 * (BB / 32), 256, lstm_smem>>>(tokens, lWhhF, lbhhF, lWhhB, lbhhB);
    gemm_tc<1><<<dim3(RR / 128, 3), 256, gemm_smem>>>(nullptr, gWihF, gWihB, gbihF, gbihB);
    gru_rec<<<2 * (BB / 32), 256, gru_smem>>>(gWhhF, gbhhF, gWhhB, gbhhB);
    final_kernel<<<BB, 256>>>(fin, attnw, attnb, linW, linb,
                              gamma, beta, mean, var, outW, outb, out);
}